// round 1
// baseline (speedup 1.0000x reference)
#include <cuda_runtime.h>
#include <math.h>

#define D_MODEL 1024
#define N_HEADS 16
#define HD      64
#define SEQ     2048
#define BATCH   2
#define M_ROWS  (BATCH * SEQ)   // 4096

// Scratch (allocation-free rule: __device__ globals)
__device__ float g_q[M_ROWS * D_MODEL];
__device__ float g_k[M_ROWS * D_MODEL];
__device__ float g_v[M_ROWS * D_MODEL];
__device__ float g_att[M_ROWS * D_MODEL];

// ---------------------------------------------------------------------------
// SGEMM: C[M,N] = A[M,K] @ B[K,N], all row-major fp32. BM=BN=128, BK=16, 8x8/thr
// ---------------------------------------------------------------------------
#define BM 128
#define BN 128
#define BK 16
#define TM 8
#define TN 8

__global__ __launch_bounds__(256) void sgemm_kernel(const float* __restrict__ A,
                                                    const float* __restrict__ B,
                                                    float* __restrict__ C,
                                                    int M, int N, int K) {
    __shared__ float As[BK][BM];
    __shared__ float Bs[BK][BN];
    const int tid  = threadIdx.x;
    const int cRow = blockIdx.y, cCol = blockIdx.x;

    A += (size_t)cRow * BM * K;
    B += cCol * BN;
    C += (size_t)cRow * BM * N + cCol * BN;

    const int innerRowA = tid >> 2;         // 0..63
    const int innerColA = (tid & 3) << 2;   // 0,4,8,12
    const int innerRowB = tid >> 5;         // 0..7
    const int innerColB = (tid & 31) << 2;  // 0..124
    const int threadRow = tid >> 4;         // 0..15
    const int threadCol = tid & 15;         // 0..15

    float acc[TM][TN] = {};
    float regM[TM], regN[TN];

    for (int bk = 0; bk < K; bk += BK) {
#pragma unroll
        for (int off = 0; off < BM; off += 64) {
            float4 t = *(const float4*)(A + (size_t)(innerRowA + off) * K + innerColA);
            As[innerColA + 0][innerRowA + off] = t.x;
            As[innerColA + 1][innerRowA + off] = t.y;
            As[innerColA + 2][innerRowA + off] = t.z;
            As[innerColA + 3][innerRowA + off] = t.w;
        }
#pragma unroll
        for (int off = 0; off < BK; off += 8) {
            *(float4*)(&Bs[innerRowB + off][innerColB]) =
                *(const float4*)(B + (size_t)(innerRowB + off) * N + innerColB);
        }
        __syncthreads();
        A += BK;
        B += (size_t)BK * N;
#pragma unroll
        for (int k = 0; k < BK; ++k) {
            *(float4*)&regM[0] = *(const float4*)&As[k][threadRow * TM];
            *(float4*)&regM[4] = *(const float4*)&As[k][threadRow * TM + 4];
            *(float4*)&regN[0] = *(const float4*)&Bs[k][threadCol * TN];
            *(float4*)&regN[4] = *(const float4*)&Bs[k][threadCol * TN + 4];
#pragma unroll
            for (int i = 0; i < TM; i++)
#pragma unroll
                for (int j = 0; j < TN; j++)
                    acc[i][j] += regM[i] * regN[j];
        }
        __syncthreads();
    }
#pragma unroll
    for (int i = 0; i < TM; i++) {
#pragma unroll
        for (int j = 0; j < TN; j += 4) {
            float4 t = make_float4(acc[i][j], acc[i][j + 1], acc[i][j + 2], acc[i][j + 3]);
            *(float4*)(C + (size_t)(threadRow * TM + i) * N + threadCol * TN + j) = t;
        }
    }
}

// ---------------------------------------------------------------------------
// Fused per-head RMSNorm + RoPE, in place on g_q / g_k.
// One warp per (b,t,h) vector of 64. Lane l owns the RoPE pair (l, l+32).
// blockIdx.y: 0 -> q buffer, 1 -> k buffer.
// ---------------------------------------------------------------------------
__global__ __launch_bounds__(256) void rmsrope_kernel(const float* __restrict__ w_q,
                                                      const float* __restrict__ w_k) {
    const int gw   = (blockIdx.x * blockDim.x + threadIdx.x) >> 5;  // vector id
    const int lane = threadIdx.x & 31;
    float* buf       = (blockIdx.y == 0) ? g_q : g_k;
    const float* w   = (blockIdx.y == 0) ? w_q : w_k;
    const int t = (gw / N_HEADS) % SEQ;   // gw = (b*SEQ + t)*H + h
    float* v = buf + (size_t)gw * HD;

    float x1 = v[lane];
    float x2 = v[lane + 32];
    float ss = x1 * x1 + x2 * x2;
#pragma unroll
    for (int o = 16; o; o >>= 1) ss += __shfl_xor_sync(0xffffffffu, ss, o);
    const float r = rsqrtf(ss * (1.0f / 64.0f) + 1e-6f);
    x1 *= r * w[lane];
    x2 *= r * w[lane + 32];

    // inv_freq[l] = 10000^(-l/32);  log2(10000)/32 = 0.41524101186...
    const float inv = exp2f(-(float)lane * 0.41524101186091903f);
    const float ang = (float)t * inv;
    float sn, cs;
    sincosf(ang, &sn, &cs);
    v[lane]      = x1 * cs - x2 * sn;
    v[lane + 32] = x2 * cs + x1 * sn;
}

// ---------------------------------------------------------------------------
// Causal flash attention, fp32 SIMT. CTA = (q-tile of 64 rows, head, batch),
// 256 threads: thread (r = tid>>2, cg = (tid&3)*16) owns row r, cols cg..cg+15.
// k tile stored TRANSPOSED in smem so all inner-loop loads are LDS.128.
// Layouts: q/k/v/att all [B, T, H, hd] row-major (GEMM-native).
// ---------------------------------------------------------------------------
#define PQ 68
#define PK 68
#define ATTN_SMEM (4 * 64 * 68 * 4)   // 69632 B

__global__ __launch_bounds__(256) void attn_kernel() {
    extern __shared__ float sm[];
    float* sq  = sm;                 // [64][PQ]  q tile (natural)
    float* skT = sq + 64 * PQ;       // [64][PK]  k tile transposed: skT[d][t]
    float* sv  = skT + 64 * PK;      // [64][PK]  v tile (natural)  sv[t][d]
    float* sp  = sv + 64 * PK;       // [64][PQ]  softmax tile P

    const int qt = blockIdx.x, h = blockIdx.y, b = blockIdx.z;
    const int tid = threadIdx.x;
    const int r   = tid >> 2;          // 0..63
    const int cg  = (tid & 3) << 4;    // 0,16,32,48
    const size_t base = ((size_t)b * SEQ) * D_MODEL + (size_t)h * HD;

    // load q tile
    for (int f = tid; f < 64 * 16; f += 256) {
        const int row = f >> 4, c4 = (f & 15) << 2;
        float4 t4 = *(const float4*)(g_q + base + (size_t)(qt * 64 + row) * D_MODEL + c4);
        *(float4*)&sq[row * PQ + c4] = t4;
    }

    float acc[16];
#pragma unroll
    for (int j = 0; j < 16; j++) acc[j] = 0.f;
    float m_run = -1e30f, l_run = 0.f;
    const int qg = qt * 64 + r;

    for (int kt = 0; kt <= qt; ++kt) {
        __syncthreads();   // protect skT/sv/sp from previous iteration's readers
        for (int f = tid; f < 64 * 16; f += 256) {
            const int row = f >> 4, c4 = (f & 15) << 2;
            const size_t goff = base + (size_t)(kt * 64 + row) * D_MODEL + c4;
            float4 k4 = *(const float4*)(g_k + goff);
            skT[(c4 + 0) * PK + row] = k4.x;
            skT[(c4 + 1) * PK + row] = k4.y;
            skT[(c4 + 2) * PK + row] = k4.z;
            skT[(c4 + 3) * PK + row] = k4.w;
            float4 v4 = *(const float4*)(g_v + goff);
            *(float4*)&sv[row * PK + c4] = v4;
        }
        __syncthreads();

        // S = q @ k^T for this thread's 16 columns
        float s[16];
#pragma unroll
        for (int j = 0; j < 16; j++) s[j] = 0.f;
#pragma unroll
        for (int kk = 0; kk < 64; kk += 4) {
            float4 q4 = *(const float4*)&sq[r * PQ + kk];
            float qreg[4] = {q4.x, q4.y, q4.z, q4.w};
#pragma unroll
            for (int u = 0; u < 4; u++) {
                const float qv = qreg[u];
                const float* kr = &skT[(kk + u) * PK + cg];
                float4 k0 = *(const float4*)(kr + 0);
                float4 k1 = *(const float4*)(kr + 4);
                float4 k2 = *(const float4*)(kr + 8);
                float4 k3 = *(const float4*)(kr + 12);
                s[0]  += qv * k0.x; s[1]  += qv * k0.y; s[2]  += qv * k0.z; s[3]  += qv * k0.w;
                s[4]  += qv * k1.x; s[5]  += qv * k1.y; s[6]  += qv * k1.z; s[7]  += qv * k1.w;
                s[8]  += qv * k2.x; s[9]  += qv * k2.y; s[10] += qv * k2.z; s[11] += qv * k2.w;
                s[12] += qv * k3.x; s[13] += qv * k3.y; s[14] += qv * k3.z; s[15] += qv * k3.w;
            }
        }

        // scale + causal mask + online softmax (row stats shared by 4 lanes)
        const float SCL = 0.125f;
        float mt = -1e30f;
        if (kt == qt) {
#pragma unroll
            for (int j = 0; j < 16; j++) {
                s[j] = (kt * 64 + cg + j <= qg) ? s[j] * SCL : -1e30f;
                mt = fmaxf(mt, s[j]);
            }
        } else {
#pragma unroll
            for (int j = 0; j < 16; j++) { s[j] *= SCL; mt = fmaxf(mt, s[j]); }
        }
        mt = fmaxf(mt, __shfl_xor_sync(0xffffffffu, mt, 1));
        mt = fmaxf(mt, __shfl_xor_sync(0xffffffffu, mt, 2));
        const float m_new = fmaxf(m_run, mt);

        float p[16];
        float lsum = 0.f;
#pragma unroll
        for (int j = 0; j < 16; j++) { p[j] = __expf(s[j] - m_new); lsum += p[j]; }
        lsum += __shfl_xor_sync(0xffffffffu, lsum, 1);
        lsum += __shfl_xor_sync(0xffffffffu, lsum, 2);
        const float alpha = __expf(m_run - m_new);
        l_run = l_run * alpha + lsum;
        m_run = m_new;
#pragma unroll
        for (int j = 0; j < 16; j++) acc[j] *= alpha;

        *(float4*)&sp[r * PQ + cg + 0]  = make_float4(p[0],  p[1],  p[2],  p[3]);
        *(float4*)&sp[r * PQ + cg + 4]  = make_float4(p[4],  p[5],  p[6],  p[7]);
        *(float4*)&sp[r * PQ + cg + 8]  = make_float4(p[8],  p[9],  p[10], p[11]);
        *(float4*)&sp[r * PQ + cg + 12] = make_float4(p[12], p[13], p[14], p[15]);
        __syncthreads();

        // O += P @ V
#pragma unroll
        for (int kk = 0; kk < 64; kk++) {
            const float pv = sp[r * PQ + kk];
            const float* vr = &sv[kk * PK + cg];
            float4 v0 = *(const float4*)(vr + 0);
            float4 v1 = *(const float4*)(vr + 4);
            float4 v2 = *(const float4*)(vr + 8);
            float4 v3 = *(const float4*)(vr + 12);
            acc[0]  += pv * v0.x; acc[1]  += pv * v0.y; acc[2]  += pv * v0.z; acc[3]  += pv * v0.w;
            acc[4]  += pv * v1.x; acc[5]  += pv * v1.y; acc[6]  += pv * v1.z; acc[7]  += pv * v1.w;
            acc[8]  += pv * v2.x; acc[9]  += pv * v2.y; acc[10] += pv * v2.z; acc[11] += pv * v2.w;
            acc[12] += pv * v3.x; acc[13] += pv * v3.y; acc[14] += pv * v3.z; acc[15] += pv * v3.w;
        }
    }

    const float invl = 1.0f / l_run;
    float* op = g_att + base + (size_t)qg * D_MODEL + cg;
    *(float4*)(op + 0)  = make_float4(acc[0]  * invl, acc[1]  * invl, acc[2]  * invl, acc[3]  * invl);
    *(float4*)(op + 4)  = make_float4(acc[4]  * invl, acc[5]  * invl, acc[6]  * invl, acc[7]  * invl);
    *(float4*)(op + 8)  = make_float4(acc[8]  * invl, acc[9]  * invl, acc[10] * invl, acc[11] * invl);
    *(float4*)(op + 12) = make_float4(acc[12] * invl, acc[13] * invl, acc[14] * invl, acc[15] * invl);
}

// ---------------------------------------------------------------------------
extern "C" void kernel_launch(void* const* d_in, const int* in_sizes, int n_in,
                              void* d_out, int out_size) {
    const float* x  = (const float*)d_in[0];
    const float* Wq = (const float*)d_in[1];
    const float* Wk = (const float*)d_in[2];
    const float* Wv = (const float*)d_in[3];
    const float* Wo = (const float*)d_in[4];
    const float* qw = (const float*)d_in[5];
    const float* kw = (const float*)d_in[6];
    float* out = (float*)d_out;

    float *qb, *kb, *vb, *ab;
    cudaGetSymbolAddress((void**)&qb, g_q);
    cudaGetSymbolAddress((void**)&kb, g_k);
    cudaGetSymbolAddress((void**)&vb, g_v);
    cudaGetSymbolAddress((void**)&ab, g_att);

    const dim3 gg(D_MODEL / BN, M_ROWS / BM);   // (8, 32)

    sgemm_kernel<<<gg, 256>>>(x, Wq, qb, M_ROWS, D_MODEL, D_MODEL);
    sgemm_kernel<<<gg, 256>>>(x, Wk, kb, M_ROWS, D_MODEL, D_MODEL);
    sgemm_kernel<<<gg, 256>>>(x, Wv, vb, M_ROWS, D_MODEL, D_MODEL);

    // 65536 head-vectors per buffer, 8 warps per block
    rmsrope_kernel<<<dim3((M_ROWS * N_HEADS) / 8, 2), 256>>>(qw, kw);

    cudaFuncSetAttribute(attn_kernel, cudaFuncAttributeMaxDynamicSharedMemorySize, ATTN_SMEM);
    attn_kernel<<<dim3(SEQ / 64, N_HEADS, BATCH), 256, ATTN_SMEM>>>();

    sgemm_kernel<<<gg, 256>>>(ab, Wo, out, M_ROWS, D_MODEL, D_MODEL);
}

// round 3
// speedup vs baseline: 1.1605x; 1.1605x over previous
#include <cuda_runtime.h>
#include <cuda_bf16.h>
#include <math.h>
#include <cstdint>

#define D_MODEL 1024
#define N_HEADS 16
#define HD      64
#define SEQ     2048
#define BATCH   2
#define M_ROWS  (BATCH * SEQ)   // 4096

// ---------------- scratch (__device__ globals; no allocs allowed) ----------
__device__ float g_q[M_ROWS * D_MODEL];
__device__ float g_k[M_ROWS * D_MODEL];
__device__ float g_v[M_ROWS * D_MODEL];
__device__ float g_att[M_ROWS * D_MODEL];
__device__ __nv_bfloat16 g_xh[M_ROWS * D_MODEL];
__device__ __nv_bfloat16 g_xl[M_ROWS * D_MODEL];
__device__ __nv_bfloat16 g_ah[M_ROWS * D_MODEL];
__device__ __nv_bfloat16 g_al[M_ROWS * D_MODEL];
__device__ __nv_bfloat16 g_wth[4 * D_MODEL * D_MODEL];  // W^T splits, [w][n][k]
__device__ __nv_bfloat16 g_wtl[4 * D_MODEL * D_MODEL];

// ---------------- PTX helpers (portable: sm_80+ features only) -------------
__device__ __forceinline__ uint32_t smem_to_u32(const void* p) {
    uint32_t a;
    asm("{ .reg .u64 t; cvta.to.shared.u64 t, %1; cvt.u32.u64 %0, t; }" : "=r"(a) : "l"(p));
    return a;
}
__device__ __forceinline__ void cpa16(uint32_t d, const void* s) {
    asm volatile("cp.async.cg.shared.global [%0], [%1], 16;" :: "r"(d), "l"(s));
}
#define CP_COMMIT() asm volatile("cp.async.commit_group;" ::: "memory")
#define LDSM_X4(r, a) \
    asm volatile("ldmatrix.sync.aligned.m8n8.x4.shared.b16 {%0,%1,%2,%3}, [%4];" \
                 : "=r"((r)[0]), "=r"((r)[1]), "=r"((r)[2]), "=r"((r)[3]) : "r"(a))
#define LDSM_X2(r, a) \
    asm volatile("ldmatrix.sync.aligned.m8n8.x2.shared.b16 {%0,%1}, [%2];" \
                 : "=r"((r)[0]), "=r"((r)[1]) : "r"(a))
__device__ __forceinline__ void mma_bf16(float* c, const uint32_t* a, const uint32_t* b) {
    asm volatile("mma.sync.aligned.m16n8k16.row.col.f32.bf16.bf16.f32 "
                 "{%0,%1,%2,%3}, {%4,%5,%6,%7}, {%8,%9}, {%0,%1,%2,%3};"
                 : "+f"(c[0]), "+f"(c[1]), "+f"(c[2]), "+f"(c[3])
                 : "r"(a[0]), "r"(a[1]), "r"(a[2]), "r"(a[3]), "r"(b[0]), "r"(b[1]));
}

// ---------------------------------------------------------------------------
// split: fp32 -> (hi, lo) bf16, elementwise
// ---------------------------------------------------------------------------
__global__ __launch_bounds__(256) void split_kernel(const float* __restrict__ src,
                                                    __nv_bfloat16* __restrict__ hi,
                                                    __nv_bfloat16* __restrict__ lo) {
    const int i = (blockIdx.x * 256 + threadIdx.x) * 4;
    float4 v = *(const float4*)(src + i);
    __nv_bfloat16 h0 = __float2bfloat16_rn(v.x), h1 = __float2bfloat16_rn(v.y);
    __nv_bfloat16 h2 = __float2bfloat16_rn(v.z), h3 = __float2bfloat16_rn(v.w);
    __nv_bfloat162* H = (__nv_bfloat162*)(hi + i);
    __nv_bfloat162* L = (__nv_bfloat162*)(lo + i);
    H[0] = __nv_bfloat162(h0, h1);
    H[1] = __nv_bfloat162(h2, h3);
    L[0] = __nv_bfloat162(__float2bfloat16_rn(v.x - __bfloat162float(h0)),
                          __float2bfloat16_rn(v.y - __bfloat162float(h1)));
    L[1] = __nv_bfloat162(__float2bfloat16_rn(v.z - __bfloat162float(h2)),
                          __float2bfloat16_rn(v.w - __bfloat162float(h3)));
}

// ---------------------------------------------------------------------------
// weight transpose + split: W[k][n] fp32 -> Wt_hi/lo[w][n][k] bf16
// ---------------------------------------------------------------------------
__global__ __launch_bounds__(256) void wsplit_kernel(const float* __restrict__ w0,
                                                     const float* __restrict__ w1,
                                                     const float* __restrict__ w2,
                                                     const float* __restrict__ w3) {
    __shared__ float t[32][33];
    const float* W = (blockIdx.z == 0) ? w0 : (blockIdx.z == 1) ? w1 : (blockIdx.z == 2) ? w2 : w3;
    const int nb = blockIdx.x * 32, kb = blockIdx.y * 32;
    const int tx = threadIdx.x & 31, ty = threadIdx.x >> 5;  // (32, 8)
#pragma unroll
    for (int i = 0; i < 32; i += 8)
        t[ty + i][tx] = W[(size_t)(kb + ty + i) * D_MODEL + nb + tx];
    __syncthreads();
    const size_t base = (size_t)blockIdx.z * D_MODEL * D_MODEL;
#pragma unroll
    for (int i = 0; i < 32; i += 8) {
        float v = t[tx][ty + i];
        __nv_bfloat16 h = __float2bfloat16_rn(v);
        size_t o = base + (size_t)(nb + ty + i) * D_MODEL + kb + tx;
        g_wth[o] = h;
        g_wtl[o] = __float2bfloat16_rn(v - __bfloat162float(h));
    }
}

// ---------------------------------------------------------------------------
// HMMA split-bf16 GEMM: C[M,1024] = A[M,1024] @ B^T  (B stored [1024,1024] [n][k])
// 128x128 CTA tile, 8 warps (2x4), 64x32 warp tile, BK=32, cp.async dbl-buffer.
// Row pad: 40 bf16 (80 B) -> conflict-free ldmatrix phases.
// ---------------------------------------------------------------------------
#define LDT   40
#define GSTG  (128 * LDT)                 // bf16 per matrix per stage (5120)
#define GEMM_SMEM (8 * GSTG * 2)          // 81920 bytes

__global__ __launch_bounds__(256) void hmma_gemm(const __nv_bfloat16* __restrict__ Ah,
                                                 const __nv_bfloat16* __restrict__ Al,
                                                 const __nv_bfloat16* __restrict__ Bh,
                                                 const __nv_bfloat16* __restrict__ Bl,
                                                 float* __restrict__ C) {
    extern __shared__ __nv_bfloat16 smg[];
    const uint32_t uAh = smem_to_u32(smg);
    const uint32_t uAl = uAh + 2 * GSTG * 2;
    const uint32_t uBh = uAh + 4 * GSTG * 2;
    const uint32_t uBl = uAh + 6 * GSTG * 2;

    const int tid = threadIdx.x, warp = tid >> 5, lane = tid & 31;
    const int tm = blockIdx.y * 128, tn = blockIdx.x * 128;
    const int wm = (warp >> 2) * 64, wn = (warp & 3) * 32;

    // per-thread copy slots: 2 x 16B chunks per matrix per stage
    const int ch0 = tid << 1;
    const int cr0 = ch0 >> 2, cc0 = (ch0 & 3);           // row, chunk-in-row
    const int cr1 = (ch0 + 1) >> 2, cc1 = ((ch0 + 1) & 3);

    auto load_stage = [&](int s, int kc) {
        {
            uint32_t so = (uint32_t)(s * GSTG + cr0 * LDT) * 2 + cc0 * 16;
            size_t ga = (size_t)(tm + cr0) * D_MODEL + kc + cc0 * 8;
            size_t gb = (size_t)(tn + cr0) * D_MODEL + kc + cc0 * 8;
            cpa16(uAh + so, Ah + ga);
            cpa16(uAl + so, Al + ga);
            cpa16(uBh + so, Bh + gb);
            cpa16(uBl + so, Bl + gb);
        }
        {
            uint32_t so = (uint32_t)(s * GSTG + cr1 * LDT) * 2 + cc1 * 16;
            size_t ga = (size_t)(tm + cr1) * D_MODEL + kc + cc1 * 8;
            size_t gb = (size_t)(tn + cr1) * D_MODEL + kc + cc1 * 8;
            cpa16(uAh + so, Ah + ga);
            cpa16(uAl + so, Al + ga);
            cpa16(uBh + so, Bh + gb);
            cpa16(uBl + so, Bl + gb);
        }
        CP_COMMIT();
    };

    float acc[4][4][4] = {};

    load_stage(0, 0);
    const int NKB = D_MODEL / 32;  // 32
    for (int kb = 0; kb < NKB; ++kb) {
        const int s = kb & 1;
        if (kb + 1 < NKB) {
            load_stage(s ^ 1, (kb + 1) * 32);
            asm volatile("cp.async.wait_group 1;" ::: "memory");
        } else {
            asm volatile("cp.async.wait_group 0;" ::: "memory");
        }
        __syncthreads();

#pragma unroll
        for (int kk = 0; kk < 2; ++kk) {
            const int k0 = kk * 16;
            // B fragments (4 n-tiles x {hi,lo})
            uint32_t bh[4][2], bl[4][2];
            const int lb = lane & 15;
            const int brow_off = (lb & 7), bk_off = (lb >> 3) * 8;
#pragma unroll
            for (int nt = 0; nt < 4; ++nt) {
                uint32_t off = (uint32_t)(s * GSTG + (wn + nt * 8 + brow_off) * LDT + k0 + bk_off) * 2;
                LDSM_X2(bh[nt], uBh + off);
                LDSM_X2(bl[nt], uBl + off);
            }
            const int arow_off = (lane & 15), ak_off = (lane >> 4) * 8;
#pragma unroll
            for (int mt = 0; mt < 4; ++mt) {
                uint32_t off = (uint32_t)(s * GSTG + (wm + mt * 16 + arow_off) * LDT + k0 + ak_off) * 2;
                uint32_t ah[4], al[4];
                LDSM_X4(ah, uAh + off);
                LDSM_X4(al, uAl + off);
#pragma unroll
                for (int nt = 0; nt < 4; ++nt) {
                    mma_bf16(acc[mt][nt], ah, bh[nt]);
                    mma_bf16(acc[mt][nt], ah, bl[nt]);
                    mma_bf16(acc[mt][nt], al, bh[nt]);
                }
            }
        }
        __syncthreads();
    }

    // epilogue
#pragma unroll
    for (int mt = 0; mt < 4; ++mt) {
#pragma unroll
        for (int nt = 0; nt < 4; ++nt) {
            const int r0 = tm + wm + mt * 16 + (lane >> 2);
            const int c0 = tn + wn + nt * 8 + 2 * (lane & 3);
            *(float2*)&C[(size_t)r0 * D_MODEL + c0] = make_float2(acc[mt][nt][0], acc[mt][nt][1]);
            *(float2*)&C[(size_t)(r0 + 8) * D_MODEL + c0] = make_float2(acc[mt][nt][2], acc[mt][nt][3]);
        }
    }
}

// ---------------------------------------------------------------------------
// Fused per-head RMSNorm + RoPE (unchanged)
// ---------------------------------------------------------------------------
__global__ __launch_bounds__(256) void rmsrope_kernel(const float* __restrict__ w_q,
                                                      const float* __restrict__ w_k) {
    const int gw   = (blockIdx.x * blockDim.x + threadIdx.x) >> 5;
    const int lane = threadIdx.x & 31;
    float* buf     = (blockIdx.y == 0) ? g_q : g_k;
    const float* w = (blockIdx.y == 0) ? w_q : w_k;
    const int t = (gw / N_HEADS) % SEQ;
    float* v = buf + (size_t)gw * HD;

    float x1 = v[lane];
    float x2 = v[lane + 32];
    float ss = x1 * x1 + x2 * x2;
#pragma unroll
    for (int o = 16; o; o >>= 1) ss += __shfl_xor_sync(0xffffffffu, ss, o);
    const float r = rsqrtf(ss * (1.0f / 64.0f) + 1e-6f);
    x1 *= r * w[lane];
    x2 *= r * w[lane + 32];
    const float inv = exp2f(-(float)lane * 0.41524101186091903f);
    const float ang = (float)t * inv;
    float sn, cs;
    sincosf(ang, &sn, &cs);
    v[lane]      = x1 * cs - x2 * sn;
    v[lane + 32] = x2 * cs + x1 * sn;
}

// ---------------------------------------------------------------------------
// Causal flash attention, fp32 SIMT (unchanged)
// ---------------------------------------------------------------------------
#define PQ 68
#define PK 68
#define ATTN_SMEM (4 * 64 * 68 * 4)

__global__ __launch_bounds__(256) void attn_kernel() {
    extern __shared__ float sm[];
    float* sq  = sm;
    float* skT = sq + 64 * PQ;
    float* sv  = skT + 64 * PK;
    float* sp  = sv + 64 * PK;

    const int qt = blockIdx.x, h = blockIdx.y, b = blockIdx.z;
    const int tid = threadIdx.x;
    const int r   = tid >> 2;
    const int cg  = (tid & 3) << 4;
    const size_t base = ((size_t)b * SEQ) * D_MODEL + (size_t)h * HD;

    for (int f = tid; f < 64 * 16; f += 256) {
        const int row = f >> 4, c4 = (f & 15) << 2;
        float4 t4 = *(const float4*)(g_q + base + (size_t)(qt * 64 + row) * D_MODEL + c4);
        *(float4*)&sq[row * PQ + c4] = t4;
    }

    float acc[16];
#pragma unroll
    for (int j = 0; j < 16; j++) acc[j] = 0.f;
    float m_run = -1e30f, l_run = 0.f;
    const int qg = qt * 64 + r;

    for (int kt = 0; kt <= qt; ++kt) {
        __syncthreads();
        for (int f = tid; f < 64 * 16; f += 256) {
            const int row = f >> 4, c4 = (f & 15) << 2;
            const size_t goff = base + (size_t)(kt * 64 + row) * D_MODEL + c4;
            float4 k4 = *(const float4*)(g_k + goff);
            skT[(c4 + 0) * PK + row] = k4.x;
            skT[(c4 + 1) * PK + row] = k4.y;
            skT[(c4 + 2) * PK + row] = k4.z;
            skT[(c4 + 3) * PK + row] = k4.w;
            float4 v4 = *(const float4*)(g_v + goff);
            *(float4*)&sv[row * PK + c4] = v4;
        }
        __syncthreads();

        float s[16];
#pragma unroll
        for (int j = 0; j < 16; j++) s[j] = 0.f;
#pragma unroll
        for (int kk = 0; kk < 64; kk += 4) {
            float4 q4 = *(const float4*)&sq[r * PQ + kk];
            float qreg[4] = {q4.x, q4.y, q4.z, q4.w};
#pragma unroll
            for (int u = 0; u < 4; u++) {
                const float qv = qreg[u];
                const float* kr = &skT[(kk + u) * PK + cg];
                float4 k0 = *(const float4*)(kr + 0);
                float4 k1 = *(const float4*)(kr + 4);
                float4 k2 = *(const float4*)(kr + 8);
                float4 k3 = *(const float4*)(kr + 12);
                s[0]  += qv * k0.x; s[1]  += qv * k0.y; s[2]  += qv * k0.z; s[3]  += qv * k0.w;
                s[4]  += qv * k1.x; s[5]  += qv * k1.y; s[6]  += qv * k1.z; s[7]  += qv * k1.w;
                s[8]  += qv * k2.x; s[9]  += qv * k2.y; s[10] += qv * k2.z; s[11] += qv * k2.w;
                s[12] += qv * k3.x; s[13] += qv * k3.y; s[14] += qv * k3.z; s[15] += qv * k3.w;
            }
        }

        const float SCL = 0.125f;
        float mt = -1e30f;
        if (kt == qt) {
#pragma unroll
            for (int j = 0; j < 16; j++) {
                s[j] = (kt * 64 + cg + j <= qg) ? s[j] * SCL : -1e30f;
                mt = fmaxf(mt, s[j]);
            }
        } else {
#pragma unroll
            for (int j = 0; j < 16; j++) { s[j] *= SCL; mt = fmaxf(mt, s[j]); }
        }
        mt = fmaxf(mt, __shfl_xor_sync(0xffffffffu, mt, 1));
        mt = fmaxf(mt, __shfl_xor_sync(0xffffffffu, mt, 2));
        const float m_new = fmaxf(m_run, mt);

        float p[16];
        float lsum = 0.f;
#pragma unroll
        for (int j = 0; j < 16; j++) { p[j] = __expf(s[j] - m_new); lsum += p[j]; }
        lsum += __shfl_xor_sync(0xffffffffu, lsum, 1);
        lsum += __shfl_xor_sync(0xffffffffu, lsum, 2);
        const float alpha = __expf(m_run - m_new);
        l_run = l_run * alpha + lsum;
        m_run = m_new;
#pragma unroll
        for (int j = 0; j < 16; j++) acc[j] *= alpha;

        *(float4*)&sp[r * PQ + cg + 0]  = make_float4(p[0],  p[1],  p[2],  p[3]);
        *(float4*)&sp[r * PQ + cg + 4]  = make_float4(p[4],  p[5],  p[6],  p[7]);
        *(float4*)&sp[r * PQ + cg + 8]  = make_float4(p[8],  p[9],  p[10], p[11]);
        *(float4*)&sp[r * PQ + cg + 12] = make_float4(p[12], p[13], p[14], p[15]);
        __syncthreads();

#pragma unroll
        for (int kk = 0; kk < 64; kk++) {
            const float pv = sp[r * PQ + kk];
            const float* vr = &sv[kk * PK + cg];
            float4 v0 = *(const float4*)(vr + 0);
            float4 v1 = *(const float4*)(vr + 4);
            float4 v2 = *(const float4*)(vr + 8);
            float4 v3 = *(const float4*)(vr + 12);
            acc[0]  += pv * v0.x; acc[1]  += pv * v0.y; acc[2]  += pv * v0.z; acc[3]  += pv * v0.w;
            acc[4]  += pv * v1.x; acc[5]  += pv * v1.y; acc[6]  += pv * v1.z; acc[7]  += pv * v1.w;
            acc[8]  += pv * v2.x; acc[9]  += pv * v2.y; acc[10] += pv * v2.z; acc[11] += pv * v2.w;
            acc[12] += pv * v3.x; acc[13] += pv * v3.y; acc[14] += pv * v3.z; acc[15] += pv * v3.w;
        }
    }

    const float invl = 1.0f / l_run;
    float* op = g_att + base + (size_t)qg * D_MODEL + cg;
    *(float4*)(op + 0)  = make_float4(acc[0]  * invl, acc[1]  * invl, acc[2]  * invl, acc[3]  * invl);
    *(float4*)(op + 4)  = make_float4(acc[4]  * invl, acc[5]  * invl, acc[6]  * invl, acc[7]  * invl);
    *(float4*)(op + 8)  = make_float4(acc[8]  * invl, acc[9]  * invl, acc[10] * invl, acc[11] * invl);
    *(float4*)(op + 12) = make_float4(acc[12] * invl, acc[13] * invl, acc[14] * invl, acc[15] * invl);
}

// ---------------------------------------------------------------------------
extern "C" void kernel_launch(void* const* d_in, const int* in_sizes, int n_in,
                              void* d_out, int out_size) {
    const float* x  = (const float*)d_in[0];
    const float* Wq = (const float*)d_in[1];
    const float* Wk = (const float*)d_in[2];
    const float* Wv = (const float*)d_in[3];
    const float* Wo = (const float*)d_in[4];
    const float* qw = (const float*)d_in[5];
    const float* kw = (const float*)d_in[6];
    float* out = (float*)d_out;

    float *qb, *kb, *vb, *ab;
    __nv_bfloat16 *xh, *xl, *ah, *al, *wth, *wtl;
    cudaGetSymbolAddress((void**)&qb, g_q);
    cudaGetSymbolAddress((void**)&kb, g_k);
    cudaGetSymbolAddress((void**)&vb, g_v);
    cudaGetSymbolAddress((void**)&ab, g_att);
    cudaGetSymbolAddress((void**)&xh, g_xh);
    cudaGetSymbolAddress((void**)&xl, g_xl);
    cudaGetSymbolAddress((void**)&ah, g_ah);
    cudaGetSymbolAddress((void**)&al, g_al);
    cudaGetSymbolAddress((void**)&wth, g_wth);
    cudaGetSymbolAddress((void**)&wtl, g_wtl);

    const int NEL = M_ROWS * D_MODEL;
    const size_t WSZ = (size_t)D_MODEL * D_MODEL;

    split_kernel<<<NEL / (256 * 4), 256>>>(x, xh, xl);
    wsplit_kernel<<<dim3(32, 32, 4), 256>>>(Wq, Wk, Wv, Wo);

    cudaFuncSetAttribute(hmma_gemm, cudaFuncAttributeMaxDynamicSharedMemorySize, GEMM_SMEM);
    const dim3 gg(D_MODEL / 128, M_ROWS / 128);  // (8, 32)
    hmma_gemm<<<gg, 256, GEMM_SMEM>>>(xh, xl, wth + 0 * WSZ, wtl + 0 * WSZ, qb);
    hmma_gemm<<<gg, 256, GEMM_SMEM>>>(xh, xl, wth + 1 * WSZ, wtl + 1 * WSZ, kb);
    hmma_gemm<<<gg, 256, GEMM_SMEM>>>(xh, xl, wth + 2 * WSZ, wtl + 2 * WSZ, vb);

    rmsrope_kernel<<<dim3((M_ROWS * N_HEADS) / 8, 2), 256>>>(qw, kw);

    cudaFuncSetAttribute(attn_kernel, cudaFuncAttributeMaxDynamicSharedMemorySize, ATTN_SMEM);
    attn_kernel<<<dim3(SEQ / 64, N_HEADS, BATCH), 256, ATTN_SMEM>>>();

    split_kernel<<<NEL / (256 * 4), 256>>>(ab, ah, al);
    hmma_gemm<<<gg, 256, GEMM_SMEM>>>(ah, al, wth + 3 * WSZ, wtl + 3 * WSZ, out);
}

// round 4
// speedup vs baseline: 3.5232x; 3.0358x over previous
#include <cuda_runtime.h>
#include <cuda_bf16.h>
#include <math.h>
#include <cstdint>

#define D_MODEL 1024
#define N_HEADS 16
#define HD      64
#define SEQ     2048
#define BATCH   2
#define M_ROWS  (BATCH * SEQ)   // 4096

// ---------------- scratch (__device__ globals; no allocs allowed) ----------
__device__ float g_q[M_ROWS * D_MODEL];
__device__ float g_k[M_ROWS * D_MODEL];
__device__ float g_v[M_ROWS * D_MODEL];
__device__ __nv_bfloat16 g_xh[M_ROWS * D_MODEL];
__device__ __nv_bfloat16 g_xl[M_ROWS * D_MODEL];
__device__ __nv_bfloat16 g_ah[M_ROWS * D_MODEL];
__device__ __nv_bfloat16 g_al[M_ROWS * D_MODEL];
__device__ __nv_bfloat16 g_qh[M_ROWS * D_MODEL];
__device__ __nv_bfloat16 g_ql[M_ROWS * D_MODEL];
__device__ __nv_bfloat16 g_kh[M_ROWS * D_MODEL];
__device__ __nv_bfloat16 g_kl[M_ROWS * D_MODEL];
__device__ __nv_bfloat16 g_vh[M_ROWS * D_MODEL];
__device__ __nv_bfloat16 g_vl[M_ROWS * D_MODEL];
__device__ __nv_bfloat16 g_wth[4 * D_MODEL * D_MODEL];  // W^T splits, [w][n][k]
__device__ __nv_bfloat16 g_wtl[4 * D_MODEL * D_MODEL];

// ---------------- PTX helpers (portable: sm_80+ features only) -------------
__device__ __forceinline__ uint32_t smem_to_u32(const void* p) {
    uint32_t a;
    asm("{ .reg .u64 t; cvta.to.shared.u64 t, %1; cvt.u32.u64 %0, t; }" : "=r"(a) : "l"(p));
    return a;
}
__device__ __forceinline__ void cpa16(uint32_t d, const void* s) {
    asm volatile("cp.async.cg.shared.global [%0], [%1], 16;" :: "r"(d), "l"(s));
}
#define CP_COMMIT() asm volatile("cp.async.commit_group;" ::: "memory")
#define LDSM_X4(r, a) \
    asm volatile("ldmatrix.sync.aligned.m8n8.x4.shared.b16 {%0,%1,%2,%3}, [%4];" \
                 : "=r"((r)[0]), "=r"((r)[1]), "=r"((r)[2]), "=r"((r)[3]) : "r"(a))
#define LDSM_X4_T(r, a) \
    asm volatile("ldmatrix.sync.aligned.m8n8.x4.trans.shared.b16 {%0,%1,%2,%3}, [%4];" \
                 : "=r"((r)[0]), "=r"((r)[1]), "=r"((r)[2]), "=r"((r)[3]) : "r"(a))
#define LDSM_X2(r, a) \
    asm volatile("ldmatrix.sync.aligned.m8n8.x2.shared.b16 {%0,%1}, [%2];" \
                 : "=r"((r)[0]), "=r"((r)[1]) : "r"(a))
__device__ __forceinline__ void mma_bf16(float* c, const uint32_t* a, const uint32_t* b) {
    asm volatile("mma.sync.aligned.m16n8k16.row.col.f32.bf16.bf16.f32 "
                 "{%0,%1,%2,%3}, {%4,%5,%6,%7}, {%8,%9}, {%0,%1,%2,%3};"
                 : "+f"(c[0]), "+f"(c[1]), "+f"(c[2]), "+f"(c[3])
                 : "r"(a[0]), "r"(a[1]), "r"(a[2]), "r"(a[3]), "r"(b[0]), "r"(b[1]));
}
__device__ __forceinline__ uint32_t pack_bf16x2(float lo, float hi) {
    uint32_t r;
    asm("cvt.rn.bf16x2.f32 %0, %1, %2;" : "=r"(r) : "f"(hi), "f"(lo));
    return r;
}
__device__ __forceinline__ float bf_lo(uint32_t u) { return __uint_as_float(u << 16); }
__device__ __forceinline__ float bf_hi(uint32_t u) { return __uint_as_float(u & 0xffff0000u); }

// ---------------------------------------------------------------------------
// split: fp32 -> (hi, lo) bf16, elementwise
// ---------------------------------------------------------------------------
__global__ __launch_bounds__(256) void split_kernel(const float* __restrict__ src,
                                                    __nv_bfloat16* __restrict__ hi,
                                                    __nv_bfloat16* __restrict__ lo) {
    const int i = (blockIdx.x * 256 + threadIdx.x) * 4;
    float4 v = *(const float4*)(src + i);
    __nv_bfloat16 h0 = __float2bfloat16_rn(v.x), h1 = __float2bfloat16_rn(v.y);
    __nv_bfloat16 h2 = __float2bfloat16_rn(v.z), h3 = __float2bfloat16_rn(v.w);
    __nv_bfloat162* H = (__nv_bfloat162*)(hi + i);
    __nv_bfloat162* L = (__nv_bfloat162*)(lo + i);
    H[0] = __nv_bfloat162(h0, h1);
    H[1] = __nv_bfloat162(h2, h3);
    L[0] = __nv_bfloat162(__float2bfloat16_rn(v.x - __bfloat162float(h0)),
                          __float2bfloat16_rn(v.y - __bfloat162float(h1)));
    L[1] = __nv_bfloat162(__float2bfloat16_rn(v.z - __bfloat162float(h2)),
                          __float2bfloat16_rn(v.w - __bfloat162float(h3)));
}

// ---------------------------------------------------------------------------
// weight transpose + split
// ---------------------------------------------------------------------------
__global__ __launch_bounds__(256) void wsplit_kernel(const float* __restrict__ w0,
                                                     const float* __restrict__ w1,
                                                     const float* __restrict__ w2,
                                                     const float* __restrict__ w3) {
    __shared__ float t[32][33];
    const float* W = (blockIdx.z == 0) ? w0 : (blockIdx.z == 1) ? w1 : (blockIdx.z == 2) ? w2 : w3;
    const int nb = blockIdx.x * 32, kb = blockIdx.y * 32;
    const int tx = threadIdx.x & 31, ty = threadIdx.x >> 5;
#pragma unroll
    for (int i = 0; i < 32; i += 8)
        t[ty + i][tx] = W[(size_t)(kb + ty + i) * D_MODEL + nb + tx];
    __syncthreads();
    const size_t base = (size_t)blockIdx.z * D_MODEL * D_MODEL;
#pragma unroll
    for (int i = 0; i < 32; i += 8) {
        float v = t[tx][ty + i];
        __nv_bfloat16 h = __float2bfloat16_rn(v);
        size_t o = base + (size_t)(nb + ty + i) * D_MODEL + kb + tx;
        g_wth[o] = h;
        g_wtl[o] = __float2bfloat16_rn(v - __bfloat162float(h));
    }
}

// ---------------------------------------------------------------------------
// HMMA split-bf16 GEMM (unchanged from R3)
// ---------------------------------------------------------------------------
#define LDT   40
#define GSTG  (128 * LDT)
#define GEMM_SMEM (8 * GSTG * 2)

__global__ __launch_bounds__(256) void hmma_gemm(const __nv_bfloat16* __restrict__ Ah,
                                                 const __nv_bfloat16* __restrict__ Al,
                                                 const __nv_bfloat16* __restrict__ Bh,
                                                 const __nv_bfloat16* __restrict__ Bl,
                                                 float* __restrict__ C) {
    extern __shared__ __nv_bfloat16 smg[];
    const uint32_t uAh = smem_to_u32(smg);
    const uint32_t uAl = uAh + 2 * GSTG * 2;
    const uint32_t uBh = uAh + 4 * GSTG * 2;
    const uint32_t uBl = uAh + 6 * GSTG * 2;

    const int tid = threadIdx.x, warp = tid >> 5, lane = tid & 31;
    const int tm = blockIdx.y * 128, tn = blockIdx.x * 128;
    const int wm = (warp >> 2) * 64, wn = (warp & 3) * 32;

    const int ch0 = tid << 1;
    const int cr0 = ch0 >> 2, cc0 = (ch0 & 3);
    const int cr1 = (ch0 + 1) >> 2, cc1 = ((ch0 + 1) & 3);

    auto load_stage = [&](int s, int kc) {
        {
            uint32_t so = (uint32_t)(s * GSTG + cr0 * LDT) * 2 + cc0 * 16;
            size_t ga = (size_t)(tm + cr0) * D_MODEL + kc + cc0 * 8;
            size_t gb = (size_t)(tn + cr0) * D_MODEL + kc + cc0 * 8;
            cpa16(uAh + so, Ah + ga);
            cpa16(uAl + so, Al + ga);
            cpa16(uBh + so, Bh + gb);
            cpa16(uBl + so, Bl + gb);
        }
        {
            uint32_t so = (uint32_t)(s * GSTG + cr1 * LDT) * 2 + cc1 * 16;
            size_t ga = (size_t)(tm + cr1) * D_MODEL + kc + cc1 * 8;
            size_t gb = (size_t)(tn + cr1) * D_MODEL + kc + cc1 * 8;
            cpa16(uAh + so, Ah + ga);
            cpa16(uAl + so, Al + ga);
            cpa16(uBh + so, Bh + gb);
            cpa16(uBl + so, Bl + gb);
        }
        CP_COMMIT();
    };

    float acc[4][4][4] = {};

    load_stage(0, 0);
    const int NKB = D_MODEL / 32;
    for (int kb = 0; kb < NKB; ++kb) {
        const int s = kb & 1;
        if (kb + 1 < NKB) {
            load_stage(s ^ 1, (kb + 1) * 32);
            asm volatile("cp.async.wait_group 1;" ::: "memory");
        } else {
            asm volatile("cp.async.wait_group 0;" ::: "memory");
        }
        __syncthreads();

#pragma unroll
        for (int kk = 0; kk < 2; ++kk) {
            const int k0 = kk * 16;
            uint32_t bh[4][2], bl[4][2];
            const int lb = lane & 15;
            const int brow_off = (lb & 7), bk_off = (lb >> 3) * 8;
#pragma unroll
            for (int nt = 0; nt < 4; ++nt) {
                uint32_t off = (uint32_t)(s * GSTG + (wn + nt * 8 + brow_off) * LDT + k0 + bk_off) * 2;
                LDSM_X2(bh[nt], uBh + off);
                LDSM_X2(bl[nt], uBl + off);
            }
            const int arow_off = (lane & 15), ak_off = (lane >> 4) * 8;
#pragma unroll
            for (int mt = 0; mt < 4; ++mt) {
                uint32_t off = (uint32_t)(s * GSTG + (wm + mt * 16 + arow_off) * LDT + k0 + ak_off) * 2;
                uint32_t ah[4], al[4];
                LDSM_X4(ah, uAh + off);
                LDSM_X4(al, uAl + off);
#pragma unroll
                for (int nt = 0; nt < 4; ++nt) {
                    mma_bf16(acc[mt][nt], ah, bh[nt]);
                    mma_bf16(acc[mt][nt], ah, bl[nt]);
                    mma_bf16(acc[mt][nt], al, bh[nt]);
                }
            }
        }
        __syncthreads();
    }

#pragma unroll
    for (int mt = 0; mt < 4; ++mt) {
#pragma unroll
        for (int nt = 0; nt < 4; ++nt) {
            const int r0 = tm + wm + mt * 16 + (lane >> 2);
            const int c0 = tn + wn + nt * 8 + 2 * (lane & 3);
            *(float2*)&C[(size_t)r0 * D_MODEL + c0] = make_float2(acc[mt][nt][0], acc[mt][nt][1]);
            *(float2*)&C[(size_t)(r0 + 8) * D_MODEL + c0] = make_float2(acc[mt][nt][2], acc[mt][nt][3]);
        }
    }
}

// ---------------------------------------------------------------------------
// Fused per-head RMSNorm + RoPE -> split bf16 outputs
// ---------------------------------------------------------------------------
__global__ __launch_bounds__(256) void rmsrope_kernel(const float* __restrict__ w_q,
                                                      const float* __restrict__ w_k) {
    const int gw   = (blockIdx.x * blockDim.x + threadIdx.x) >> 5;
    const int lane = threadIdx.x & 31;
    const float* src = (blockIdx.y == 0) ? g_q : g_k;
    const float* w   = (blockIdx.y == 0) ? w_q : w_k;
    __nv_bfloat16* oh = (blockIdx.y == 0) ? g_qh : g_kh;
    __nv_bfloat16* ol = (blockIdx.y == 0) ? g_ql : g_kl;
    const int t = (gw / N_HEADS) % SEQ;
    const size_t base = (size_t)gw * HD;

    float x1 = src[base + lane];
    float x2 = src[base + lane + 32];
    float ss = x1 * x1 + x2 * x2;
#pragma unroll
    for (int o = 16; o; o >>= 1) ss += __shfl_xor_sync(0xffffffffu, ss, o);
    const float r = rsqrtf(ss * (1.0f / 64.0f) + 1e-6f);
    x1 *= r * w[lane];
    x2 *= r * w[lane + 32];
    const float inv = exp2f(-(float)lane * 0.41524101186091903f);
    const float ang = (float)t * inv;
    float sn, cs;
    sincosf(ang, &sn, &cs);
    const float y1 = x1 * cs - x2 * sn;
    const float y2 = x2 * cs + x1 * sn;

    __nv_bfloat16 h1 = __float2bfloat16_rn(y1);
    __nv_bfloat16 h2 = __float2bfloat16_rn(y2);
    oh[base + lane]      = h1;
    oh[base + lane + 32] = h2;
    ol[base + lane]      = __float2bfloat16_rn(y1 - __bfloat162float(h1));
    ol[base + lane + 32] = __float2bfloat16_rn(y2 - __bfloat162float(h2));
}

// ---------------------------------------------------------------------------
// HMMA flash attention, split-bf16. CTA = 128 q-rows x head x batch, 8 warps.
// K-block 64, double-buffered K/V hi/lo, V loaded via ldmatrix.trans.
// ---------------------------------------------------------------------------
#define LDK   72
#define QELEM (128 * LDK)   // 9216 elems per q matrix
#define KSTG  (64 * LDK)    // 4608 elems per kv matrix per stage
#define ATT_SMEM ((2 * QELEM + 8 * KSTG) * 2)   // 110592 B

__global__ __launch_bounds__(256) void attn_hmma() {
    extern __shared__ char smA[];
    const uint32_t u0  = smem_to_u32(smA);
    const uint32_t uQh = u0;
    const uint32_t uQl = u0 + QELEM * 2;

    const int tid = threadIdx.x, warp = tid >> 5, lane = tid & 31;
    const int qt = (int)(gridDim.x - 1) - (int)blockIdx.x;   // long CTAs first
    const int h = blockIdx.y, b = blockIdx.z;
    const int wm = warp * 16;
    const size_t gq0 = ((size_t)b * SEQ + (size_t)qt * 128) * D_MODEL + h * HD;

    // ---- load q tile (hi: chunks c=0..3, lo: c=4..7)
#pragma unroll
    for (int c = 0; c < 8; ++c) {
        const int r = ((c & 3) * 32 + (tid >> 3)) & 127;
        const int col8 = (tid & 7) * 8;
        const __nv_bfloat16* src = (c < 4) ? g_qh : g_ql;
        const uint32_t dst = ((c < 4) ? uQh : uQl) + (uint32_t)(r * LDK + col8) * 2;
        cpa16(dst, src + gq0 + (size_t)r * D_MODEL + col8);
    }
    CP_COMMIT();

    auto load_kv = [&](int s, int kb) {
        const uint32_t ub = u0 + (2 * QELEM + s * 4 * KSTG) * 2;
#pragma unroll
        for (int c = 0; c < 8; ++c) {
            const int mat = c >> 1;
            const int r = ((c & 1) * 32 + (tid >> 3)) & 63;
            const int col8 = (tid & 7) * 8;
            const __nv_bfloat16* src = (mat == 0) ? g_kh : (mat == 1) ? g_kl
                                     : (mat == 2) ? g_vh : g_vl;
            const size_t ga = ((size_t)b * SEQ + (size_t)kb * 64 + r) * D_MODEL + h * HD + col8;
            cpa16(ub + (uint32_t)(mat * KSTG + r * LDK + col8) * 2, src + ga);
        }
        CP_COMMIT();
    };

    load_kv(0, 0);
    asm volatile("cp.async.wait_group 0;" ::: "memory");
    __syncthreads();

    // ---- q fragments (A, m16k16), once
    uint32_t qfh[4][4], qfl[4][4];
#pragma unroll
    for (int ks = 0; ks < 4; ++ks) {
        const uint32_t off = (uint32_t)((wm + (lane & 15)) * LDK + ks * 16 + ((lane >> 4) << 3)) * 2;
        LDSM_X4(qfh[ks], uQh + off);
        LDSM_X4(qfl[ks], uQl + off);
    }

    float acc[8][4] = {};
    float m0 = -1e30f, m1 = -1e30f, l0 = 0.f, l1 = 0.f;
    const int nkb = 2 * qt + 2;
    const int qrow0 = qt * 128 + wm;

    for (int kb = 0; kb < nkb; ++kb) {
        const int s = kb & 1;
        if (kb + 1 < nkb) {
            load_kv(s ^ 1, kb + 1);
            asm volatile("cp.async.wait_group 1;" ::: "memory");
        } else {
            asm volatile("cp.async.wait_group 0;" ::: "memory");
        }
        __syncthreads();

        const bool active = (kb * 64 <= qrow0 + 15);
        if (active) {
            const uint32_t uKh = u0 + (2 * QELEM + s * 4 * KSTG) * 2;
            const uint32_t uKl = uKh + KSTG * 2;
            const uint32_t uVh = uKh + 2 * KSTG * 2;
            const uint32_t uVl = uKh + 3 * KSTG * 2;

            // ---- S = q k^T (3-term split)
            float sc[8][4] = {};
#pragma unroll
            for (int ks = 0; ks < 4; ++ks) {
#pragma unroll
                for (int np = 0; np < 4; ++np) {
                    const uint32_t boff = (uint32_t)((np * 16 + (lane & 7) + ((lane >> 4) << 3)) * LDK
                                                     + ks * 16 + (((lane >> 3) & 1) << 3)) * 2;
                    uint32_t bh[4], bl[4];
                    LDSM_X4(bh, uKh + boff);
                    LDSM_X4(bl, uKl + boff);
                    mma_bf16(sc[2 * np],     qfh[ks], &bh[0]);
                    mma_bf16(sc[2 * np],     qfh[ks], &bl[0]);
                    mma_bf16(sc[2 * np],     qfl[ks], &bh[0]);
                    mma_bf16(sc[2 * np + 1], qfh[ks], &bh[2]);
                    mma_bf16(sc[2 * np + 1], qfh[ks], &bl[2]);
                    mma_bf16(sc[2 * np + 1], qfl[ks], &bh[2]);
                }
            }

            // ---- scale + mask + online softmax
            const float SCL = 0.125f;
            const bool domask = (kb * 64 + 63 > qrow0);
            const int r0 = qrow0 + (lane >> 2);
            float mt0 = -1e30f, mt1 = -1e30f;
#pragma unroll
            for (int nt = 0; nt < 8; ++nt) {
#pragma unroll
                for (int j = 0; j < 4; ++j) sc[nt][j] *= SCL;
                if (domask) {
                    const int colb = kb * 64 + nt * 8 + 2 * (lane & 3);
                    if (colb     > r0)     sc[nt][0] = -1e30f;
                    if (colb + 1 > r0)     sc[nt][1] = -1e30f;
                    if (colb     > r0 + 8) sc[nt][2] = -1e30f;
                    if (colb + 1 > r0 + 8) sc[nt][3] = -1e30f;
                }
                mt0 = fmaxf(mt0, fmaxf(sc[nt][0], sc[nt][1]));
                mt1 = fmaxf(mt1, fmaxf(sc[nt][2], sc[nt][3]));
            }
            mt0 = fmaxf(mt0, __shfl_xor_sync(0xffffffffu, mt0, 1));
            mt0 = fmaxf(mt0, __shfl_xor_sync(0xffffffffu, mt0, 2));
            mt1 = fmaxf(mt1, __shfl_xor_sync(0xffffffffu, mt1, 1));
            mt1 = fmaxf(mt1, __shfl_xor_sync(0xffffffffu, mt1, 2));
            const float mn0 = fmaxf(m0, mt0), mn1 = fmaxf(m1, mt1);
            const float a0 = __expf(m0 - mn0), a1 = __expf(m1 - mn1);
            m0 = mn0; m1 = mn1;

            float s0 = 0.f, s1 = 0.f;
            uint32_t ph[4][4], pl[4][4];
#pragma unroll
            for (int nt = 0; nt < 8; ++nt) {
                const float p0 = __expf(sc[nt][0] - mn0);
                const float p1 = __expf(sc[nt][1] - mn0);
                const float p2 = __expf(sc[nt][2] - mn1);
                const float p3 = __expf(sc[nt][3] - mn1);
                s0 += p0 + p1;
                s1 += p2 + p3;
                const uint32_t hA = pack_bf16x2(p0, p1);
                const uint32_t hB = pack_bf16x2(p2, p3);
                const uint32_t lA = pack_bf16x2(p0 - bf_lo(hA), p1 - bf_hi(hA));
                const uint32_t lB = pack_bf16x2(p2 - bf_lo(hB), p3 - bf_hi(hB));
                const int ks = nt >> 1, pos = (nt & 1) * 2;
                ph[ks][pos] = hA; ph[ks][pos + 1] = hB;
                pl[ks][pos] = lA; pl[ks][pos + 1] = lB;
            }
            s0 += __shfl_xor_sync(0xffffffffu, s0, 1);
            s0 += __shfl_xor_sync(0xffffffffu, s0, 2);
            s1 += __shfl_xor_sync(0xffffffffu, s1, 1);
            s1 += __shfl_xor_sync(0xffffffffu, s1, 2);
            l0 = l0 * a0 + s0;
            l1 = l1 * a1 + s1;
#pragma unroll
            for (int nt = 0; nt < 8; ++nt) {
                acc[nt][0] *= a0; acc[nt][1] *= a0;
                acc[nt][2] *= a1; acc[nt][3] *= a1;
            }

            // ---- O += P V (3-term split, V via ldmatrix.trans)
#pragma unroll
            for (int ks = 0; ks < 4; ++ks) {
#pragma unroll
                for (int np = 0; np < 4; ++np) {
                    const uint32_t voff = (uint32_t)((ks * 16 + (lane & 7) + (((lane >> 3) & 1) << 3)) * LDK
                                                     + np * 16 + ((lane >> 4) << 3)) * 2;
                    uint32_t vh4[4], vl4[4];
                    LDSM_X4_T(vh4, uVh + voff);
                    LDSM_X4_T(vl4, uVl + voff);
                    mma_bf16(acc[2 * np],     ph[ks], &vh4[0]);
                    mma_bf16(acc[2 * np],     ph[ks], &vl4[0]);
                    mma_bf16(acc[2 * np],     pl[ks], &vh4[0]);
                    mma_bf16(acc[2 * np + 1], ph[ks], &vh4[2]);
                    mma_bf16(acc[2 * np + 1], ph[ks], &vl4[2]);
                    mma_bf16(acc[2 * np + 1], pl[ks], &vh4[2]);
                }
            }
        }
        __syncthreads();
    }

    // ---- epilogue: normalize, split to bf16 hi/lo, write O-proj A buffers
    const float i0 = 1.0f / l0, i1 = 1.0f / l1;
    const size_t gr0 = ((size_t)b * SEQ + qrow0 + (lane >> 2)) * D_MODEL + h * HD + 2 * (lane & 3);
#pragma unroll
    for (int nt = 0; nt < 8; ++nt) {
        const float o0 = acc[nt][0] * i0, o1 = acc[nt][1] * i0;
        const float o2 = acc[nt][2] * i1, o3 = acc[nt][3] * i1;
        const uint32_t hA = pack_bf16x2(o0, o1);
        const uint32_t hB = pack_bf16x2(o2, o3);
        const uint32_t lA = pack_bf16x2(o0 - bf_lo(hA), o1 - bf_hi(hA));
        const uint32_t lB = pack_bf16x2(o2 - bf_lo(hB), o3 - bf_hi(hB));
        *(uint32_t*)&g_ah[gr0 + nt * 8]                 = hA;
        *(uint32_t*)&g_al[gr0 + nt * 8]                 = lA;
        *(uint32_t*)&g_ah[gr0 + 8 * D_MODEL + nt * 8]   = hB;
        *(uint32_t*)&g_al[gr0 + 8 * D_MODEL + nt * 8]   = lB;
    }
}

// ---------------------------------------------------------------------------
extern "C" void kernel_launch(void* const* d_in, const int* in_sizes, int n_in,
                              void* d_out, int out_size) {
    const float* x  = (const float*)d_in[0];
    const float* Wq = (const float*)d_in[1];
    const float* Wk = (const float*)d_in[2];
    const float* Wv = (const float*)d_in[3];
    const float* Wo = (const float*)d_in[4];
    const float* qw = (const float*)d_in[5];
    const float* kw = (const float*)d_in[6];
    float* out = (float*)d_out;

    float *qb, *kb, *vb;
    __nv_bfloat16 *xh, *xl, *ah, *al, *vh, *vl, *wth, *wtl;
    cudaGetSymbolAddress((void**)&qb, g_q);
    cudaGetSymbolAddress((void**)&kb, g_k);
    cudaGetSymbolAddress((void**)&vb, g_v);
    cudaGetSymbolAddress((void**)&xh, g_xh);
    cudaGetSymbolAddress((void**)&xl, g_xl);
    cudaGetSymbolAddress((void**)&ah, g_ah);
    cudaGetSymbolAddress((void**)&al, g_al);
    cudaGetSymbolAddress((void**)&vh, g_vh);
    cudaGetSymbolAddress((void**)&vl, g_vl);
    cudaGetSymbolAddress((void**)&wth, g_wth);
    cudaGetSymbolAddress((void**)&wtl, g_wtl);

    const int NEL = M_ROWS * D_MODEL;
    const size_t WSZ = (size_t)D_MODEL * D_MODEL;

    split_kernel<<<NEL / (256 * 4), 256>>>(x, xh, xl);
    wsplit_kernel<<<dim3(32, 32, 4), 256>>>(Wq, Wk, Wv, Wo);

    cudaFuncSetAttribute(hmma_gemm, cudaFuncAttributeMaxDynamicSharedMemorySize, GEMM_SMEM);
    const dim3 gg(D_MODEL / 128, M_ROWS / 128);
    hmma_gemm<<<gg, 256, GEMM_SMEM>>>(xh, xl, wth + 0 * WSZ, wtl + 0 * WSZ, qb);
    hmma_gemm<<<gg, 256, GEMM_SMEM>>>(xh, xl, wth + 1 * WSZ, wtl + 1 * WSZ, kb);
    hmma_gemm<<<gg, 256, GEMM_SMEM>>>(xh, xl, wth + 2 * WSZ, wtl + 2 * WSZ, vb);

    rmsrope_kernel<<<dim3((M_ROWS * N_HEADS) / 8, 2), 256>>>(qw, kw);
    split_kernel<<<NEL / (256 * 4), 256>>>(vb, vh, vl);

    cudaFuncSetAttribute(attn_hmma, cudaFuncAttributeMaxDynamicSharedMemorySize, ATT_SMEM);
    attn_hmma<<<dim3(SEQ / 128, N_HEADS, BATCH), 256, ATT_SMEM>>>();

    hmma_gemm<<<gg, 256, GEMM_SMEM>>>(ah, al, wth + 3 * WSZ, wtl + 3 * WSZ, out);
}